// round 9
// baseline (speedup 1.0000x reference)
#include <cuda_runtime.h>
#include <cstdint>

// EdgeBlock fused MLP, TF32 mma.sync. Round 9 = R7 base + 4x2 warp grid:
//  warp (wr,wc): rows wr*32..+32 (2 m-tiles), cols wc*32..+32 (4 n-tiles)
//  -> B fragments reused across both m-tiles (L1 B traffic halved)
// x = [edges(32) | nodes[send](32) | nodes[recv](32) | globals[batch](16)]  (K=112)
// h = relu(x @ W1 + b1) (64);  y = h @ W2 + b2 (32)

#define TILE_M 128
#define NTHREADS 256

#define SX_STRIDE 116       // 112 + pad -> conflict-free fragment LDS
#define SH_STRIDE 68
#define SMEM_FLOATS (TILE_M * SX_STRIDE)   // 14848
#define SMEM_BYTES  (SMEM_FLOATS * 4)      // 59392 -> 3 CTAs/SM

// fragment-packed weights (R7 layout): W1P[(ks*8+nt)*32 + lane] = (b0,b1)
__device__ float2 d_W1P[14 * 8 * 32];
__device__ float2 d_W2P[8 * 4 * 32];

__device__ __forceinline__ float tf32_rna(float x) {
    unsigned u;
    asm("cvt.rna.tf32.f32 %0, %1;" : "=r"(u) : "f"(x));
    return __uint_as_float(u);
}

__device__ __forceinline__ void mma_tf32_16x8x8(float* c, const unsigned* a,
                                                unsigned b0, unsigned b1) {
    asm volatile(
        "mma.sync.aligned.m16n8k8.row.col.f32.tf32.tf32.f32 "
        "{%0,%1,%2,%3}, {%4,%5,%6,%7}, {%8,%9}, {%0,%1,%2,%3};"
        : "+f"(c[0]), "+f"(c[1]), "+f"(c[2]), "+f"(c[3])
        : "r"(a[0]), "r"(a[1]), "r"(a[2]), "r"(a[3]), "r"(b0), "r"(b1));
}

__global__ void prep_weights(const float* __restrict__ W1,
                             const float* __restrict__ W2) {
    int i = blockIdx.x * blockDim.x + threadIdx.x;
    if (i < 14 * 8 * 32) {
        int lane = i & 31, nt = (i >> 5) & 7, ks = i >> 8;
        int g = lane >> 2, c = lane & 3;
        float b0 = W1[(ks * 8 + c) * 64 + nt * 8 + g];
        float b1 = W1[(ks * 8 + c + 4) * 64 + nt * 8 + g];
        d_W1P[i] = make_float2(tf32_rna(b0), tf32_rna(b1));
    }
    if (i < 8 * 4 * 32) {
        int lane = i & 31, nt = (i >> 5) & 3, ks = i >> 7;
        int g = lane >> 2, c = lane & 3;
        float b0 = W2[(ks * 8 + c) * 32 + nt * 8 + g];
        float b1 = W2[(ks * 8 + c + 4) * 32 + nt * 8 + g];
        d_W2P[i] = make_float2(tf32_rna(b0), tf32_rna(b1));
    }
}

__global__ void __launch_bounds__(NTHREADS, 3)
edgeblock_kernel(const float* __restrict__ nodes,
                 const float* __restrict__ edges,
                 const float* __restrict__ graph_globals,
                 const int*   __restrict__ send,
                 const int*   __restrict__ recv,
                 const int*   __restrict__ batch_edges,
                 const float* __restrict__ b1,
                 const float* __restrict__ b2,
                 float*       __restrict__ out) {
    extern __shared__ float sm[];
    float* sX = sm;                      // [128][116] tf32 (aliased by sH)

    const int t  = threadIdx.x;
    const int e0 = blockIdx.x * TILE_M;

    // ---- stage x tile (coalesced float4 reads, tf32 convert; R7-identical) ----
    for (int i = t; i < TILE_M * 8; i += NTHREADS) {
        int e = i >> 3, seg = i & 7;
        float4 v = *reinterpret_cast<const float4*>(edges + (size_t)(e0 + e) * 32 + seg * 4);
        float* d = sX + e * SX_STRIDE + seg * 4;
        d[0] = tf32_rna(v.x); d[1] = tf32_rna(v.y);
        d[2] = tf32_rna(v.z); d[3] = tf32_rna(v.w);
    }
    for (int i = t; i < TILE_M * 8; i += NTHREADS) {
        int e = i >> 3, seg = i & 7;
        int n = __ldg(send + e0 + e);
        float4 v = *reinterpret_cast<const float4*>(nodes + (size_t)n * 32 + seg * 4);
        float* d = sX + e * SX_STRIDE + 32 + seg * 4;
        d[0] = tf32_rna(v.x); d[1] = tf32_rna(v.y);
        d[2] = tf32_rna(v.z); d[3] = tf32_rna(v.w);
    }
    for (int i = t; i < TILE_M * 8; i += NTHREADS) {
        int e = i >> 3, seg = i & 7;
        int n = __ldg(recv + e0 + e);
        float4 v = *reinterpret_cast<const float4*>(nodes + (size_t)n * 32 + seg * 4);
        float* d = sX + e * SX_STRIDE + 64 + seg * 4;
        d[0] = tf32_rna(v.x); d[1] = tf32_rna(v.y);
        d[2] = tf32_rna(v.z); d[3] = tf32_rna(v.w);
    }
    for (int i = t; i < TILE_M * 4; i += NTHREADS) {
        int e = i >> 2, seg = i & 3;
        int g = __ldg(batch_edges + e0 + e);
        float4 v = *reinterpret_cast<const float4*>(graph_globals + (size_t)g * 16 + seg * 4);
        float* d = sX + e * SX_STRIDE + 96 + seg * 4;
        d[0] = tf32_rna(v.x); d[1] = tf32_rna(v.y);
        d[2] = tf32_rna(v.z); d[3] = tf32_rna(v.w);
    }
    __syncthreads();

    // ---- warp grid: wr in 0..3 (rows), wc in 0..1 (cols) ----
    const int lane = t & 31;
    const int w    = t >> 5;
    const int wr   = w & 3;
    const int wc   = w >> 2;
    const int g    = lane >> 2;
    const int c    = lane & 3;
    const int R    = wr * 32;            // row base; m-tiles at R and R+16

    const float2* w1p = d_W1P + lane;
    const float2* w2p = d_W2P + lane;

    // ---- layer 1: warp computes rows [R,R+32) x cols [wc*32, wc*32+32) ----
    float acc[2][4][4];
#pragma unroll
    for (int mt = 0; mt < 2; mt++)
#pragma unroll
        for (int nl = 0; nl < 4; nl++)
#pragma unroll
            for (int q = 0; q < 4; q++) acc[mt][nl][q] = 0.0f;

#pragma unroll
    for (int ks = 0; ks < 14; ks++) {
        const int k = ks * 8;
        unsigned a[2][4];
#pragma unroll
        for (int mt = 0; mt < 2; mt++) {
            int r = R + mt * 16 + g;
            a[mt][0] = __float_as_uint(sX[r * SX_STRIDE + k + c]);
            a[mt][1] = __float_as_uint(sX[(r + 8) * SX_STRIDE + k + c]);
            a[mt][2] = __float_as_uint(sX[r * SX_STRIDE + k + c + 4]);
            a[mt][3] = __float_as_uint(sX[(r + 8) * SX_STRIDE + k + c + 4]);
        }
#pragma unroll
        for (int nl = 0; nl < 4; nl++) {
            float2 b = __ldg(w1p + (ks * 8 + wc * 4 + nl) * 32);
            unsigned b0 = __float_as_uint(b.x), b1 = __float_as_uint(b.y);
            mma_tf32_16x8x8(acc[0][nl], a[0], b0, b1);
            mma_tf32_16x8x8(acc[1][nl], a[1], b0, b1);
        }
    }
    __syncthreads();   // done reading sX; sH aliases it

    // ---- bias + relu + tf32 -> smem h ----
    float* sH = sm;   // [128][68]
#pragma unroll
    for (int mt = 0; mt < 2; mt++) {
        int r = R + mt * 16 + g;
#pragma unroll
        for (int nl = 0; nl < 4; nl++) {
            int col = (wc * 4 + nl) * 8 + 2 * c;
            float2 bb = __ldg(reinterpret_cast<const float2*>(b1 + col));
            float h0 = tf32_rna(fmaxf(acc[mt][nl][0] + bb.x, 0.0f));
            float h1 = tf32_rna(fmaxf(acc[mt][nl][1] + bb.y, 0.0f));
            float h2 = tf32_rna(fmaxf(acc[mt][nl][2] + bb.x, 0.0f));
            float h3 = tf32_rna(fmaxf(acc[mt][nl][3] + bb.y, 0.0f));
            sH[r * SH_STRIDE + col]           = h0;
            sH[r * SH_STRIDE + col + 1]       = h1;
            sH[(r + 8) * SH_STRIDE + col]     = h2;
            sH[(r + 8) * SH_STRIDE + col + 1] = h3;
        }
    }
    __syncthreads();

    // ---- layer 2: rows [R,R+32) x cols [wc*16, wc*16+16) ----
    float d2[2][2][4];
#pragma unroll
    for (int mt = 0; mt < 2; mt++)
#pragma unroll
        for (int nl = 0; nl < 2; nl++)
#pragma unroll
            for (int q = 0; q < 4; q++) d2[mt][nl][q] = 0.0f;

#pragma unroll
    for (int ks = 0; ks < 8; ks++) {
        const int k = ks * 8;
        unsigned a[2][4];
#pragma unroll
        for (int mt = 0; mt < 2; mt++) {
            int r = R + mt * 16 + g;
            a[mt][0] = __float_as_uint(sH[r * SH_STRIDE + k + c]);
            a[mt][1] = __float_as_uint(sH[(r + 8) * SH_STRIDE + k + c]);
            a[mt][2] = __float_as_uint(sH[r * SH_STRIDE + k + c + 4]);
            a[mt][3] = __float_as_uint(sH[(r + 8) * SH_STRIDE + k + c + 4]);
        }
#pragma unroll
        for (int nl = 0; nl < 2; nl++) {
            float2 b = __ldg(w2p + (ks * 4 + wc * 2 + nl) * 32);
            unsigned b0 = __float_as_uint(b.x), b1 = __float_as_uint(b.y);
            mma_tf32_16x8x8(d2[0][nl], a[0], b0, b1);
            mma_tf32_16x8x8(d2[1][nl], a[1], b0, b1);
        }
    }

    // ---- epilogue: bias + store out[E,32] ----
#pragma unroll
    for (int mt = 0; mt < 2; mt++) {
        int r = R + mt * 16 + g;
#pragma unroll
        for (int nl = 0; nl < 2; nl++) {
            int col = (wc * 2 + nl) * 8 + 2 * c;
            float2 bb = __ldg(reinterpret_cast<const float2*>(b2 + col));
            float2 v0 = make_float2(d2[mt][nl][0] + bb.x, d2[mt][nl][1] + bb.y);
            float2 v1 = make_float2(d2[mt][nl][2] + bb.x, d2[mt][nl][3] + bb.y);
            *reinterpret_cast<float2*>(out + (size_t)(e0 + r) * 32 + col)     = v0;
            *reinterpret_cast<float2*>(out + (size_t)(e0 + r + 8) * 32 + col) = v1;
        }
    }
}

extern "C" void kernel_launch(void* const* d_in, const int* in_sizes, int n_in,
                              void* d_out, int out_size) {
    const float* nodes         = (const float*)d_in[0];
    const float* edges         = (const float*)d_in[1];
    const float* graph_globals = (const float*)d_in[2];
    const int*   send          = (const int*)d_in[3];
    const int*   recv          = (const int*)d_in[4];
    const int*   batch_edges   = (const int*)d_in[5];
    const float* W1            = (const float*)d_in[6];
    const float* b1            = (const float*)d_in[7];
    const float* W2            = (const float*)d_in[8];
    const float* b2            = (const float*)d_in[9];
    float*       out           = (float*)d_out;

    const int n_edges = in_sizes[1] / 32;          // 1,600,000
    const int grid    = (n_edges + TILE_M - 1) / TILE_M;

    prep_weights<<<(14 * 8 * 32 + 255) / 256, 256>>>(W1, W2);

    cudaFuncSetAttribute(edgeblock_kernel,
                         cudaFuncAttributeMaxDynamicSharedMemorySize, SMEM_BYTES);
    edgeblock_kernel<<<grid, NTHREADS, SMEM_BYTES>>>(
        nodes, edges, graph_globals, send, recv, batch_edges,
        b1, b2, out);
}

// round 11
// speedup vs baseline: 1.7000x; 1.7000x over previous
#include <cuda_runtime.h>
#include <cstdint>

// EdgeBlock fused MLP, TF32 mma.sync. Round 10 = R7 MMA core (unchanged, fits
// the 80-reg envelope) + row-contiguous staging:
//  one warp stages one full x row per step (lane = column) -> STS conflict-free
//  (1 wf vs 4 wf), LDG still one 128B row per warp-inst; indices preloaded and
//  shfl-broadcast.
// x = [edges(32) | nodes[send](32) | nodes[recv](32) | globals[batch](16)]  (K=112)
// h = relu(x @ W1 + b1) (64);  y = h @ W2 + b2 (32)

#define TILE_M 128
#define NTHREADS 256

#define SX_STRIDE 116       // conflict-free fragment LDS (116 mod 32 = 20)
#define SH_STRIDE 68
#define SMEM_FLOATS (TILE_M * SX_STRIDE)   // 14848
#define SMEM_BYTES  (SMEM_FLOATS * 4)      // 59392 -> 3 CTAs/SM

// fragment-packed weights (R7 layout): W1P[(ks*8+nt)*32 + lane] = (b0,b1)
__device__ float2 d_W1P[14 * 8 * 32];
__device__ float2 d_W2P[8 * 4 * 32];

__device__ __forceinline__ float tf32_rna(float x) {
    unsigned u;
    asm("cvt.rna.tf32.f32 %0, %1;" : "=r"(u) : "f"(x));
    return __uint_as_float(u);
}

__device__ __forceinline__ void mma_tf32_16x8x8(float* c, const unsigned* a,
                                                unsigned b0, unsigned b1) {
    asm volatile(
        "mma.sync.aligned.m16n8k8.row.col.f32.tf32.tf32.f32 "
        "{%0,%1,%2,%3}, {%4,%5,%6,%7}, {%8,%9}, {%0,%1,%2,%3};"
        : "+f"(c[0]), "+f"(c[1]), "+f"(c[2]), "+f"(c[3])
        : "r"(a[0]), "r"(a[1]), "r"(a[2]), "r"(a[3]), "r"(b0), "r"(b1));
}

__global__ void prep_weights(const float* __restrict__ W1,
                             const float* __restrict__ W2) {
    int i = blockIdx.x * blockDim.x + threadIdx.x;
    if (i < 14 * 8 * 32) {
        int lane = i & 31, nt = (i >> 5) & 7, ks = i >> 8;
        int g = lane >> 2, c = lane & 3;
        float b0 = W1[(ks * 8 + c) * 64 + nt * 8 + g];
        float b1 = W1[(ks * 8 + c + 4) * 64 + nt * 8 + g];
        d_W1P[i] = make_float2(tf32_rna(b0), tf32_rna(b1));
    }
    if (i < 8 * 4 * 32) {
        int lane = i & 31, nt = (i >> 5) & 3, ks = i >> 7;
        int g = lane >> 2, c = lane & 3;
        float b0 = W2[(ks * 8 + c) * 32 + nt * 8 + g];
        float b1 = W2[(ks * 8 + c + 4) * 32 + nt * 8 + g];
        d_W2P[i] = make_float2(tf32_rna(b0), tf32_rna(b1));
    }
}

__global__ void __launch_bounds__(NTHREADS, 3)
edgeblock_kernel(const float* __restrict__ nodes,
                 const float* __restrict__ edges,
                 const float* __restrict__ graph_globals,
                 const int*   __restrict__ send,
                 const int*   __restrict__ recv,
                 const int*   __restrict__ batch_edges,
                 const float* __restrict__ b1,
                 const float* __restrict__ b2,
                 float*       __restrict__ out) {
    extern __shared__ float sm[];
    float* sX = sm;                      // [128][116] tf32 (aliased by sH)

    const int t    = threadIdx.x;
    const int e0   = blockIdx.x * TILE_M;
    const int lane = t & 31;
    const int w    = t >> 5;             // warp id 0..7
    const int rbase = w * 16;            // this warp stages rows [rbase, rbase+16)

    // ---- stage x tile: one warp = one full row per step (conflict-free STS) ----
    {
        int idxS = __ldg(send        + e0 + rbase + (lane & 15));
        int idxR = __ldg(recv        + e0 + rbase + (lane & 15));
        int idxB = __ldg(batch_edges + e0 + rbase + (lane & 15));
#pragma unroll
        for (int rr = 0; rr < 16; rr++) {
            int e = rbase + rr;
            float* row = sX + e * SX_STRIDE;
            row[lane] = tf32_rna(edges[(size_t)(e0 + e) * 32 + lane]);
            int ns = __shfl_sync(0xffffffffu, idxS, rr);
            row[32 + lane] = tf32_rna(nodes[(size_t)ns * 32 + lane]);
            int nr = __shfl_sync(0xffffffffu, idxR, rr);
            row[64 + lane] = tf32_rna(nodes[(size_t)nr * 32 + lane]);
        }
        // globals: 16 cols -> two rows per step via half-warps
#pragma unroll
        for (int rr = 0; rr < 8; rr++) {
            int e  = rbase + rr * 2 + (lane >> 4);
            int gb = __shfl_sync(0xffffffffu, idxB, rr * 2 + (lane >> 4));
            sX[e * SX_STRIDE + 96 + (lane & 15)] =
                tf32_rna(graph_globals[(size_t)gb * 16 + (lane & 15)]);
        }
    }
    __syncthreads();

    // ---- layer 1: [128,112] @ [112,64]; warp w owns rows [w*16, w*16+16) ----
    const int g = lane >> 2;
    const int c = lane & 3;
    const int r = rbase + g;

    const float2* w1p = d_W1P + lane;   // + (ks*8+nt)*32
    const float2* w2p = d_W2P + lane;   // + (ks*4+nt)*32

    float acc[8][4];
#pragma unroll
    for (int nt = 0; nt < 8; nt++)
#pragma unroll
        for (int q = 0; q < 4; q++) acc[nt][q] = 0.0f;

#pragma unroll
    for (int ks = 0; ks < 14; ks++) {
        const int k = ks * 8;
        unsigned a[4];
        a[0] = __float_as_uint(sX[r * SX_STRIDE + k + c]);
        a[1] = __float_as_uint(sX[(r + 8) * SX_STRIDE + k + c]);
        a[2] = __float_as_uint(sX[r * SX_STRIDE + k + c + 4]);
        a[3] = __float_as_uint(sX[(r + 8) * SX_STRIDE + k + c + 4]);
#pragma unroll
        for (int nt = 0; nt < 8; nt++) {
            float2 b = __ldg(w1p + (ks * 8 + nt) * 32);
            mma_tf32_16x8x8(acc[nt], a, __float_as_uint(b.x), __float_as_uint(b.y));
        }
    }
    __syncthreads();   // done reading sX; sH aliases it

    // ---- bias + relu + tf32 -> smem h ----
    float* sH = sm;   // [128][68]
#pragma unroll
    for (int nt = 0; nt < 8; nt++) {
        int col = nt * 8 + 2 * c;
        float bb0 = __ldg(b1 + col), bb1 = __ldg(b1 + col + 1);
        float h0 = fmaxf(acc[nt][0] + bb0, 0.0f);
        float h1 = fmaxf(acc[nt][1] + bb1, 0.0f);
        float h2 = fmaxf(acc[nt][2] + bb0, 0.0f);
        float h3 = fmaxf(acc[nt][3] + bb1, 0.0f);
        sH[r * SH_STRIDE + col]           = tf32_rna(h0);
        sH[r * SH_STRIDE + col + 1]       = tf32_rna(h1);
        sH[(r + 8) * SH_STRIDE + col]     = tf32_rna(h2);
        sH[(r + 8) * SH_STRIDE + col + 1] = tf32_rna(h3);
    }
    __syncthreads();

    // ---- layer 2: [128,64] @ [64,32] ----
    float d2[4][4];
#pragma unroll
    for (int nt = 0; nt < 4; nt++)
#pragma unroll
        for (int q = 0; q < 4; q++) d2[nt][q] = 0.0f;

#pragma unroll
    for (int ks = 0; ks < 8; ks++) {
        const int k = ks * 8;
        unsigned a[4];
        a[0] = __float_as_uint(sH[r * SH_STRIDE + k + c]);
        a[1] = __float_as_uint(sH[(r + 8) * SH_STRIDE + k + c]);
        a[2] = __float_as_uint(sH[r * SH_STRIDE + k + c + 4]);
        a[3] = __float_as_uint(sH[(r + 8) * SH_STRIDE + k + c + 4]);
#pragma unroll
        for (int nt = 0; nt < 4; nt++) {
            float2 b = __ldg(w2p + (ks * 4 + nt) * 32);
            mma_tf32_16x8x8(d2[nt], a, __float_as_uint(b.x), __float_as_uint(b.y));
        }
    }

    // ---- epilogue: bias + store out[E,32] ----
#pragma unroll
    for (int nt = 0; nt < 4; nt++) {
        int col = nt * 8 + 2 * c;
        float bb0 = __ldg(b2 + col), bb1 = __ldg(b2 + col + 1);
        float2 v0 = make_float2(d2[nt][0] + bb0, d2[nt][1] + bb1);
        float2 v1 = make_float2(d2[nt][2] + bb0, d2[nt][3] + bb1);
        *reinterpret_cast<float2*>(out + (size_t)(e0 + r) * 32 + col)     = v0;
        *reinterpret_cast<float2*>(out + (size_t)(e0 + r + 8) * 32 + col) = v1;
    }
}

extern "C" void kernel_launch(void* const* d_in, const int* in_sizes, int n_in,
                              void* d_out, int out_size) {
    const float* nodes         = (const float*)d_in[0];
    const float* edges         = (const float*)d_in[1];
    const float* graph_globals = (const float*)d_in[2];
    const int*   send          = (const int*)d_in[3];
    const int*   recv          = (const int*)d_in[4];
    const int*   batch_edges   = (const int*)d_in[5];
    const float* W1            = (const float*)d_in[6];
    const float* b1            = (const float*)d_in[7];
    const float* W2            = (const float*)d_in[8];
    const float* b2            = (const float*)d_in[9];
    float*       out           = (float*)d_out;

    const int n_edges = in_sizes[1] / 32;          // 1,600,000
    const int grid    = (n_edges + TILE_M - 1) / TILE_M;

    prep_weights<<<(14 * 8 * 32 + 255) / 256, 256>>>(W1, W2);

    cudaFuncSetAttribute(edgeblock_kernel,
                         cudaFuncAttributeMaxDynamicSharedMemorySize, SMEM_BYTES);
    edgeblock_kernel<<<grid, NTHREADS, SMEM_BYTES>>>(
        nodes, edges, graph_globals, send, recv, batch_edges,
        b1, b2, out);
}

// round 12
// speedup vs baseline: 1.7522x; 1.0307x over previous
#include <cuda_runtime.h>
#include <cstdint>

// EdgeBlock fused MLP, TF32 mma.sync. Round 12 = R11 + shuffle h relayout:
//  layer-1 C-fragments are permuted into layer-2 A-fragments via __shfl_sync
//  (intra-quad exchange) -> h smem round-trip (STS+LDS) and 2 barriers removed.
// x = [edges(32) | nodes[send](32) | nodes[recv](32) | globals[batch](16)]  (K=112)
// h = relu(x @ W1 + b1) (64);  y = h @ W2 + b2 (32)

#define TILE_M 128
#define NTHREADS 256

#define SX_STRIDE 116       // conflict-free fragment LDS (116 mod 32 = 20)
#define SMEM_FLOATS (TILE_M * SX_STRIDE)   // 14848
#define SMEM_BYTES  (SMEM_FLOATS * 4)      // 59392 -> 3 CTAs/SM

// fragment-packed weights: W1P[(ks*8+nt)*32 + lane] = (b0,b1)
__device__ float2 d_W1P[14 * 8 * 32];
__device__ float2 d_W2P[8 * 4 * 32];

__device__ __forceinline__ float tf32_rna(float x) {
    unsigned u;
    asm("cvt.rna.tf32.f32 %0, %1;" : "=r"(u) : "f"(x));
    return __uint_as_float(u);
}

__device__ __forceinline__ void mma_tf32_16x8x8(float* c, const unsigned* a,
                                                unsigned b0, unsigned b1) {
    asm volatile(
        "mma.sync.aligned.m16n8k8.row.col.f32.tf32.tf32.f32 "
        "{%0,%1,%2,%3}, {%4,%5,%6,%7}, {%8,%9}, {%0,%1,%2,%3};"
        : "+f"(c[0]), "+f"(c[1]), "+f"(c[2]), "+f"(c[3])
        : "r"(a[0]), "r"(a[1]), "r"(a[2]), "r"(a[3]), "r"(b0), "r"(b1));
}

__global__ void prep_weights(const float* __restrict__ W1,
                             const float* __restrict__ W2) {
    int i = blockIdx.x * blockDim.x + threadIdx.x;
    if (i < 14 * 8 * 32) {
        int lane = i & 31, nt = (i >> 5) & 7, ks = i >> 8;
        int g = lane >> 2, c = lane & 3;
        float b0 = W1[(ks * 8 + c) * 64 + nt * 8 + g];
        float b1 = W1[(ks * 8 + c + 4) * 64 + nt * 8 + g];
        d_W1P[i] = make_float2(tf32_rna(b0), tf32_rna(b1));
    }
    if (i < 8 * 4 * 32) {
        int lane = i & 31, nt = (i >> 5) & 3, ks = i >> 7;
        int g = lane >> 2, c = lane & 3;
        float b0 = W2[(ks * 8 + c) * 32 + nt * 8 + g];
        float b1 = W2[(ks * 8 + c + 4) * 32 + nt * 8 + g];
        d_W2P[i] = make_float2(tf32_rna(b0), tf32_rna(b1));
    }
}

__global__ void __launch_bounds__(NTHREADS, 3)
edgeblock_kernel(const float* __restrict__ nodes,
                 const float* __restrict__ edges,
                 const float* __restrict__ graph_globals,
                 const int*   __restrict__ send,
                 const int*   __restrict__ recv,
                 const int*   __restrict__ batch_edges,
                 const float* __restrict__ b1,
                 const float* __restrict__ b2,
                 float*       __restrict__ out) {
    extern __shared__ float sm[];
    float* sX = sm;                      // [128][116] tf32

    const int t     = threadIdx.x;
    const int e0    = blockIdx.x * TILE_M;
    const int lane  = t & 31;
    const int w     = t >> 5;            // warp id 0..7
    const int rbase = w * 16;            // warp owns rows [rbase, rbase+16)

    // ---- stage x tile: one warp = one full row per step (conflict-free STS) ----
    {
        int idxS = __ldg(send        + e0 + rbase + (lane & 15));
        int idxR = __ldg(recv        + e0 + rbase + (lane & 15));
        int idxB = __ldg(batch_edges + e0 + rbase + (lane & 15));
#pragma unroll
        for (int rr = 0; rr < 16; rr++) {
            int e = rbase + rr;
            float* row = sX + e * SX_STRIDE;
            row[lane] = tf32_rna(edges[(size_t)(e0 + e) * 32 + lane]);
            int ns = __shfl_sync(0xffffffffu, idxS, rr);
            row[32 + lane] = tf32_rna(nodes[(size_t)ns * 32 + lane]);
            int nr = __shfl_sync(0xffffffffu, idxR, rr);
            row[64 + lane] = tf32_rna(nodes[(size_t)nr * 32 + lane]);
        }
#pragma unroll
        for (int rr = 0; rr < 8; rr++) {
            int e  = rbase + rr * 2 + (lane >> 4);
            int gb = __shfl_sync(0xffffffffu, idxB, rr * 2 + (lane >> 4));
            sX[e * SX_STRIDE + 96 + (lane & 15)] =
                tf32_rna(graph_globals[(size_t)gb * 16 + (lane & 15)]);
        }
    }
    __syncthreads();

    // ---- layer 1: [128,112] @ [112,64]; warp w owns rows [w*16, w*16+16) ----
    const int g = lane >> 2;
    const int c = lane & 3;
    const int r = rbase + g;

    const float2* w1p = d_W1P + lane;   // + (ks*8+nt)*32
    const float2* w2p = d_W2P + lane;   // + (ks*4+nt)*32

    float acc[8][4];
#pragma unroll
    for (int nt = 0; nt < 8; nt++)
#pragma unroll
        for (int q = 0; q < 4; q++) acc[nt][q] = 0.0f;

#pragma unroll
    for (int ks = 0; ks < 14; ks++) {
        const int k = ks * 8;
        unsigned a[4];
        a[0] = __float_as_uint(sX[r * SX_STRIDE + k + c]);
        a[1] = __float_as_uint(sX[(r + 8) * SX_STRIDE + k + c]);
        a[2] = __float_as_uint(sX[r * SX_STRIDE + k + c + 4]);
        a[3] = __float_as_uint(sX[(r + 8) * SX_STRIDE + k + c + 4]);
#pragma unroll
        for (int nt = 0; nt < 8; nt++) {
            float2 b = __ldg(w1p + (ks * 8 + nt) * 32);
            mma_tf32_16x8x8(acc[nt], a, __float_as_uint(b.x), __float_as_uint(b.y));
        }
    }

    // ---- bias + relu + tf32 in registers (C-fragment layout) ----
#pragma unroll
    for (int nt = 0; nt < 8; nt++) {
        int col = nt * 8 + 2 * c;
        float bb0 = __ldg(b1 + col), bb1 = __ldg(b1 + col + 1);
        acc[nt][0] = tf32_rna(fmaxf(acc[nt][0] + bb0, 0.0f));
        acc[nt][1] = tf32_rna(fmaxf(acc[nt][1] + bb1, 0.0f));
        acc[nt][2] = tf32_rna(fmaxf(acc[nt][2] + bb0, 0.0f));
        acc[nt][3] = tf32_rna(fmaxf(acc[nt][3] + bb1, 0.0f));
    }

    // ---- layer 2: [128,64] @ [64,32]; A-fragments built by intra-quad shuffles ----
    // Requester (g,c) needs h[g][8ks+c], h[g+8][8ks+c], h[g][8ks+c+4], h[g+8][8ks+c+4].
    // Holder of col j in block ks: lane 4*g + (j>>1), component (row<8?0:2)+(j&1).
    const int src0 = 4 * g + (c >> 1);
    const int src1 = src0 + 2;
    const bool odd = (c & 1);

    float d2[4][4];
#pragma unroll
    for (int nt = 0; nt < 4; nt++)
#pragma unroll
        for (int q = 0; q < 4; q++) d2[nt][q] = 0.0f;

#pragma unroll
    for (int ks = 0; ks < 8; ks++) {
        float v00 = __shfl_sync(0xffffffffu, acc[ks][0], src0);
        float v01 = __shfl_sync(0xffffffffu, acc[ks][1], src0);
        float v02 = __shfl_sync(0xffffffffu, acc[ks][2], src0);
        float v03 = __shfl_sync(0xffffffffu, acc[ks][3], src0);
        float v10 = __shfl_sync(0xffffffffu, acc[ks][0], src1);
        float v11 = __shfl_sync(0xffffffffu, acc[ks][1], src1);
        float v12 = __shfl_sync(0xffffffffu, acc[ks][2], src1);
        float v13 = __shfl_sync(0xffffffffu, acc[ks][3], src1);
        unsigned a[4];
        a[0] = __float_as_uint(odd ? v01 : v00);   // h[g][8ks+c]
        a[1] = __float_as_uint(odd ? v03 : v02);   // h[g+8][8ks+c]
        a[2] = __float_as_uint(odd ? v11 : v10);   // h[g][8ks+c+4]
        a[3] = __float_as_uint(odd ? v13 : v12);   // h[g+8][8ks+c+4]
#pragma unroll
        for (int nt = 0; nt < 4; nt++) {
            float2 b = __ldg(w2p + (ks * 4 + nt) * 32);
            mma_tf32_16x8x8(d2[nt], a, __float_as_uint(b.x), __float_as_uint(b.y));
        }
    }

    // ---- epilogue: bias + store out[E,32] ----
#pragma unroll
    for (int nt = 0; nt < 4; nt++) {
        int col = nt * 8 + 2 * c;
        float bb0 = __ldg(b2 + col), bb1 = __ldg(b2 + col + 1);
        float2 v0 = make_float2(d2[nt][0] + bb0, d2[nt][1] + bb1);
        float2 v1 = make_float2(d2[nt][2] + bb0, d2[nt][3] + bb1);
        *reinterpret_cast<float2*>(out + (size_t)(e0 + r) * 32 + col)     = v0;
        *reinterpret_cast<float2*>(out + (size_t)(e0 + r + 8) * 32 + col) = v1;
    }
}

extern "C" void kernel_launch(void* const* d_in, const int* in_sizes, int n_in,
                              void* d_out, int out_size) {
    const float* nodes         = (const float*)d_in[0];
    const float* edges         = (const float*)d_in[1];
    const float* graph_globals = (const float*)d_in[2];
    const int*   send          = (const int*)d_in[3];
    const int*   recv          = (const int*)d_in[4];
    const int*   batch_edges   = (const int*)d_in[5];
    const float* W1            = (const float*)d_in[6];
    const float* b1            = (const float*)d_in[7];
    const float* W2            = (const float*)d_in[8];
    const float* b2            = (const float*)d_in[9];
    float*       out           = (float*)d_out;

    const int n_edges = in_sizes[1] / 32;          // 1,600,000
    const int grid    = (n_edges + TILE_M - 1) / TILE_M;

    prep_weights<<<(14 * 8 * 32 + 255) / 256, 256>>>(W1, W2);

    cudaFuncSetAttribute(edgeblock_kernel,
                         cudaFuncAttributeMaxDynamicSharedMemorySize, SMEM_BYTES);
    edgeblock_kernel<<<grid, NTHREADS, SMEM_BYTES>>>(
        nodes, edges, graph_globals, send, recv, batch_edges,
        b1, b2, out);
}